// round 15
// baseline (speedup 1.0000x reference)
#include <cuda_runtime.h>
#include <cstdint>

#define NA     17064
#define KTOP   1000
#define NBINS  16384
#define CCAP   4096
#define NT     1024
#define B      16
#define NCTA   128
#define FULL   0xffffffffu

typedef unsigned long long u64;

// ---------------- static device scratch ----------------
__device__ unsigned ghist[B][NBINS];      // zero-init; re-zeroed each pass
__device__ unsigned gcnt[B];
__device__ u64      gkey[B][CCAP];
__device__ float    gssc[B][KTOP];        // top-K records, scattered by rank
__device__ unsigned gslab[B][KTOP];
__device__ float4   gsbox[B][KTOP];
__device__ int      gmxi[B], gmni[B];     // global mx/mn (float-as-int, >=0)
__device__ unsigned gbarc[B][8];          // per-batch epoch barrier counters

// Exact sigmoid: float exp via double exp (correctly rounded to float =>
// matches faithful libm expf), then float add + div as XLA expands logistic.
__device__ __forceinline__ float sigx(float x) {
    float t = (float)exp(-(double)x);
    return __fdiv_rn(1.0f, __fadd_rn(1.0f, t));
}
// Fast approximate sigmoid — superset selection only.
__device__ __forceinline__ float siga(float x) {
    return __fdividef(1.0f, 1.0f + __expf(-x));
}
// per-batch barrier (8 CTAs), release/acquire, graph-replay safe
__device__ __forceinline__ void bbarrier(int b, int k) {
    __syncthreads();
    if (threadIdx.x == 0) {
        unsigned* addr = &gbarc[b][k];
        unsigned old;
        asm volatile("atom.add.release.gpu.global.u32 %0, [%1], 1;"
                     : "=r"(old) : "l"(addr) : "memory");
        unsigned target = ((old >> 3) + 1u) << 3;
        unsigned v;
        do {
            asm volatile("ld.acquire.gpu.global.u32 %0, [%1];"
                         : "=r"(v) : "l"(addr) : "memory");
        } while (v < target);
    }
    __syncthreads();
}
// guarded warp suffix-sum (inclusive from high lanes)
__device__ __forceinline__ unsigned suffix_sum(unsigned v, int lane) {
#pragma unroll
    for (int o = 1; o < 32; o <<= 1) {
        unsigned t = __shfl_down_sync(FULL, v, o);
        if (lane + o < 32) v += t;
    }
    return v;
}

// ---- dynamic smem arena (bytes) ----
#define OFF_MAT    0          // u32[1000][32] = 128000 (class matrix) | P3: keys
#define OFF_BX     128000     // 5 * f32[1000] = 20000
#define OFF_FLAT   148000     // u32[1000]
#define OFF_DIAG   152000     // u32[1024]
#define OFF_RNZ    156096     // u32[1024]
#define SMEM_TOTAL 160256
extern __shared__ unsigned char smem_raw[];

__global__ void __launch_bounds__(NT, 1)
fcos_persist(const float* __restrict__ cls, const float* __restrict__ ctr,
             const float* __restrict__ reg, const float* __restrict__ coords,
             const float* __restrict__ pstr, float* __restrict__ out)
{
    const int cta  = blockIdx.x;
    const int b    = cta >> 3;
    const int r    = cta & 7;
    const int tid  = threadIdx.x;
    const int lane = tid & 31;
    const int wid  = tid >> 5;

    __shared__ unsigned chunk[1024];
    __shared__ unsigned supr[32];
    __shared__ float redmax[32], redmin[32];
    __shared__ unsigned s_thr;
    __shared__ unsigned swcnt2[32], swv2[32], soff2[32];
    __shared__ unsigned s_nc, s_nval;
    __shared__ unsigned snzw[32], srem[32];

    const float4* clsB = (const float4*)cls + (size_t)b * NA;
    const float*  ctrB = ctr + (size_t)b * NA;

    // ============ P1: resets + approx-score histogram =======================
    if (r == 0 && tid == 0) {
        gcnt[b] = 0;
        gmxi[b] = 0;                        // float 0.0 bits (coords >= 0)
        gmni[b] = __float_as_int(1e9f);
    }
    for (int i = r * NT + tid; i < NA; i += 8 * NT) {
        float4 c = clsB[i];
        float m = fmaxf(fmaxf(c.x, c.y), fmaxf(c.z, c.w));   // sigmoid monotone
        float score = __fsqrt_rn(siga(m) * siga(ctrB[i]));
        atomicAdd(&ghist[b][__float_as_uint(score) >> 16], 1u);
    }
    bbarrier(b, 0);

    // ============ P2: threshold (warp-parallel suffix scans) ================
    { unsigned s = 0; int base = tid * 16;
#pragma unroll
      for (int q = 0; q < 16; ++q) s += ghist[b][base + q];
      chunk[tid] = s; }
    __syncthreads();
    { unsigned s = chunk[wid * 32 + lane];
#pragma unroll
      for (int o = 16; o; o >>= 1) s += __shfl_xor_sync(FULL, s, o);
      if (lane == 0) supr[wid] = s; }
    __syncthreads();
    if (wid == 0) {
        unsigned suf = suffix_sum(supr[lane], lane);
        unsigned m1  = __ballot_sync(FULL, suf >= KTOP);
        int sblk     = 31 - __clz(m1);
        unsigned above = (sblk < 31) ? __shfl_sync(FULL, suf, sblk + 1) : 0u;
        unsigned cs  = suffix_sum(chunk[sblk * 32 + lane], lane);
        unsigned m2  = __ballot_sync(FULL, cs + above >= KTOP);
        int cc       = 31 - __clz(m2);
        unsigned above2 = above + ((cc < 31) ? __shfl_sync(FULL, cs, cc + 1) : 0u);
        int binbase  = (sblk * 32 + cc) * 16;
        unsigned bs  = suffix_sum((lane < 16) ? ghist[b][binbase + lane] : 0u, lane);
        unsigned m3  = __ballot_sync(FULL, bs + above2 >= KTOP);
        int bb       = 31 - __clz(m3);
        if (lane == 0) {
            int T = binbase + bb;
            s_thr = (T > 0) ? (unsigned)(T - 1) : 0u;   // one-bin superset margin
        }
    }
    __syncthreads();
    const unsigned T = s_thr;

    // ============ P2b: fused compact + exact rescore ========================
    for (int i = r * NT + tid; i < NA; i += 8 * NT) {
        float4 c = clsB[i];
        float xs0 = c.x, xs1 = c.y, xs2 = c.z, xs3 = c.w;
        float m = fmaxf(fmaxf(xs0, xs1), fmaxf(xs2, xs3));
        float ctrv = ctrB[i];
        float sa = __fsqrt_rn(siga(m) * siga(ctrv));
        if ((__float_as_uint(sa) >> 16) >= T) {
            unsigned p = atomicAdd(&gcnt[b], 1u);
            if (p < CCAP) {
                int im = 0; float mm = xs0;
                if (xs1 > mm) { mm = xs1; im = 1; }
                if (xs2 > mm) { mm = xs2; im = 2; }
                if (xs3 > mm) { mm = xs3; im = 3; }
                float sm = sigx(mm);                    // == max of 4 sigmoids
                int lab = im;
                if (im > 0) {                           // first-argmax tie guard
                    float lim = mm - 1e-4f;
                    if (xs0 > lim || (im > 1 && xs1 > lim) || (im > 2 && xs2 > lim)) {
                        if (xs0 > lim && sigx(xs0) == sm) lab = 0;
                        else if (im > 1 && xs1 > lim && sigx(xs1) == sm) lab = 1;
                        else if (im > 2 && xs2 > lim && sigx(xs2) == sm) lab = 2;
                    }
                }
                float sctr  = sigx(ctrv);
                float score = __fsqrt_rn(__fmul_rn(sm, sctr));
                gkey[b][p] = ((u64)__float_as_uint(score) << 32)
                           | ((u64)(0x7FFFu - (unsigned)i) << 4) | (u64)(lab + 1);
            }
        }
    }
    bbarrier(b, 1);

    int C = (int)gcnt[b]; if (C > CCAP) C = CCAP;

    // ============ P3: rank slice + scatter top-K records + mx/mn ===========
    {
        u64* skeys = (u64*)smem_raw;                          // 32KB
        unsigned* srank = (unsigned*)(smem_raw + 32768);      // <=512
        for (int i = tid; i < C; i += NT) skeys[i] = gkey[b][i];
        int i0 = (r * C) >> 3, i1 = ((r + 1) * C) >> 3;
        int ni = i1 - i0;
        for (int t = tid; t < ni; t += NT) srank[t] = 0u;
        __syncthreads();

        // balanced partial counts: (i, 1/8 j-slice) pairs
        int total = ni * 8;
        for (int t = tid; t < total; t += NT) {
            int ii = t >> 3, part = t & 7;
            u64 ki = skeys[i0 + ii];
            int j0 = (part * C) >> 3, j1 = ((part + 1) * C) >> 3;
            unsigned cnt = 0;
#pragma unroll 8
            for (int j = j0; j < j1; ++j) cnt += (skeys[j] > ki) ? 1u : 0u;
            if (cnt) atomicAdd(&srank[ii], cnt);
        }
        __syncthreads();

        // rank<KTOP: build clipped box, scatter record by rank
        float lmax = -1000000000.0f, lmin = 1000000000.0f;
        for (int t = tid; t < ni; t += NT) {
            unsigned rk = srank[t];
            if (rk < KTOP) {
                u64 key = skeys[i0 + t];
                float score = __uint_as_float((unsigned)(key >> 32));
                int label   = (int)(key & 0xFull);
                int idx = 0x7FFF - (int)((key >> 4) & 0x7FFFull);
                bool validf = (score >= 0.05f);

                float4 r4 = ((const float4*)reg)[(size_t)b * NA + idx];
                float2 xy = ((const float2*)coords)[idx];
                float  st = pstr[idx];
                float x1 = __fsub_rn(xy.x, __fmul_rn(r4.x, st));
                float y1 = __fsub_rn(xy.y, __fmul_rn(r4.y, st));
                float x2 = __fadd_rn(xy.x, __fmul_rn(r4.z, st));
                float y2 = __fadd_rn(xy.y, __fmul_rn(r4.w, st));
                x1 = fminf(fmaxf(x1, 0.0f), 1023.0f);
                y1 = fminf(fmaxf(y1, 0.0f), 799.0f);
                x2 = fminf(fmaxf(x2, 0.0f), 1023.0f);
                y2 = fminf(fmaxf(y2, 0.0f), 799.0f);

                gsbox[b][rk] = make_float4(x1, y1, x2, y2);
                gssc[b][rk]  = score;
                gslab[b][rk] = (unsigned)label;
                if (validf) {
                    lmax = fmaxf(lmax, fmaxf(fmaxf(x1, y1), fmaxf(x2, y2)));
                    lmin = fminf(lmin, fminf(fminf(x1, y1), fminf(x2, y2)));
                }
            }
        }
        // CTA-reduce mx/mn, single atomic per CTA
#pragma unroll
        for (int o = 16; o; o >>= 1) {
            lmax = fmaxf(lmax, __shfl_xor_sync(FULL, lmax, o));
            lmin = fminf(lmin, __shfl_xor_sync(FULL, lmin, o));
        }
        if (lane == 0) { redmax[wid] = lmax; redmin[wid] = lmin; }
        __syncthreads();
        if (wid == 0) {
            float mx = redmax[lane], mn = redmin[lane];
#pragma unroll
            for (int o = 16; o; o >>= 1) {
                mx = fmaxf(mx, __shfl_xor_sync(FULL, mx, o));
                mn = fminf(mn, __shfl_xor_sync(FULL, mn, o));
            }
            if (lane == 0) {
                if (mx >= 0.0f)   atomicMax(&gmxi[b], __float_as_int(mx));
                if (mn < 1e9f)    atomicMin(&gmni[b], __float_as_int(mn));
            }
        }
        // zero this CTA's hist slice
        for (int i = r * 2048 + tid; i < (r + 1) * 2048; i += NT) ghist[b][i] = 0;
        // r==0: zero output tail if C < KTOP (normally empty)
        if (r == 0) {
            for (int q = C + tid; q < KTOP; q += NT) {
                out[(size_t)b * KTOP + q] = 0.0f;
                out[(size_t)(B * KTOP) + (size_t)b * KTOP + q] = 0.0f;
                size_t obase = (size_t)(2 * B * KTOP) + ((size_t)b * KTOP + q) * 4;
                out[obase + 0] = 0.0f; out[obase + 1] = 0.0f;
                out[obase + 2] = 0.0f; out[obase + 3] = 0.0f;
            }
        }
    }
    bbarrier(b, 2);

    // ============ P4: per-class matrix + NMS + outputs (CTA r<4 = class r) ==
    if (r >= 4) return;
    {
        unsigned* smat  = (unsigned*)(smem_raw + OFF_MAT);   // [1000][32]
        float* sx1c = (float*)(smem_raw + OFF_BX);
        float* sy1c = sx1c + KTOP; float* sx2c = sy1c + KTOP;
        float* sy2c = sx2c + KTOP; float* sarc = sy2c + KTOP;
        unsigned* sflatc = (unsigned*)(smem_raw + OFF_FLAT);
        unsigned* sdiagc = (unsigned*)(smem_raw + OFF_DIAG);
        unsigned* srownz = (unsigned*)(smem_raw + OFF_RNZ);

        const int c = r;
        const int CK = (C < KTOP) ? C : KTOP;
        float mxv = __int_as_float(gmxi[b]);
        float mnv = __int_as_float(gmni[b]);
        float off = __fmul_rn((float)(c + 1), __fadd_rn(__fsub_rn(mxv, mnv), 1.0f));

        // membership scan (one padded trip; CK <= 1000 < NT)
        int q = tid;
        bool member = (q < CK) && (gslab[b][q] == (unsigned)(c + 1));
        float scq = member ? gssc[b][q] : 0.0f;
        unsigned bal  = __ballot_sync(FULL, member);
        unsigned balv = __ballot_sync(FULL, member && (scq >= 0.05f));
        if (lane == 0) { swcnt2[wid] = __popc(bal); swv2[wid] = __popc(balv); }
        __syncthreads();
        if (wid == 0) {
            unsigned v = swcnt2[lane];
            unsigned inc = v;
#pragma unroll
            for (int o = 1; o < 32; o <<= 1) {
                unsigned t2 = __shfl_up_sync(FULL, inc, o);
                if (lane >= o) inc += t2;
            }
            soff2[lane] = inc - v;
            unsigned tv = swv2[lane];
#pragma unroll
            for (int o = 16; o; o >>= 1) tv += __shfl_xor_sync(FULL, tv, o);
            if (lane == 31) s_nc = inc;
            if (lane == 0)  s_nval = tv;
        }
        __syncthreads();
        const int nc   = (int)s_nc;
        const int nval = (int)s_nval;

        if (member) {
            unsigned pos = soff2[wid] + __popc(bal & ((1u << lane) - 1u));
            float4 bx = gsbox[b][q];
            float a  = __fadd_rn(bx.x, off), bb2 = __fadd_rn(bx.y, off);
            float cc3 = __fadd_rn(bx.z, off), dd = __fadd_rn(bx.w, off);
            sx1c[pos] = a;  sy1c[pos] = bb2;
            sx2c[pos] = cc3; sy2c[pos] = dd;
            sarc[pos] = __fmul_rn(__fsub_rn(cc3, a), __fsub_rn(dd, bb2));
            sflatc[pos] = (unsigned)q;
        }
        __syncthreads();

        // matrix in smem: warp per row
        int nw = (nc + 31) >> 5;
        for (int pos = wid; pos < nc; pos += 32) {
            float ax1 = sx1c[pos], ay1 = sy1c[pos], ax2 = sx2c[pos],
                  ay2 = sy2c[pos], aa = sarc[pos];
            unsigned myword = 0;
            int jc0 = (pos + 1) >> 5;
            for (int jc = jc0; jc < nw; ++jc) {
                int j = jc * 32 + lane;
                bool sup = false;
                if (j > pos && j < nc) {
                    float ix1 = fmaxf(ax1, sx1c[j]);
                    float iy1 = fmaxf(ay1, sy1c[j]);
                    float ix2 = fminf(ax2, sx2c[j]);
                    float iy2 = fminf(ay2, sy2c[j]);
                    float iw  = fmaxf(__fsub_rn(ix2, ix1), 0.0f);
                    float ih  = fmaxf(__fsub_rn(iy2, iy1), 0.0f);
                    float inter = __fmul_rn(iw, ih);
                    float uni = fmaxf(__fsub_rn(__fadd_rn(aa, sarc[j]), inter), 1e-9f);
                    sup = __fdiv_rn(inter, uni) > 0.5f;
                }
                unsigned wbits = __ballot_sync(FULL, sup);
                if (lane == jc) myword = wbits;
            }
            smat[pos * 32 + lane] = myword;
            if (lane == (pos >> 5)) sdiagc[pos] = myword;
            unsigned any = __ballot_sync(FULL, myword != 0u);
            if (lane == 0) srownz[pos] = any;
        }
        __syncthreads();

        // per-block nz words (single full-block trip)
        { unsigned v = (tid < nc) ? srownz[tid] : 0u;
          unsigned bal2 = __ballot_sync(FULL, v != 0u);
          if (lane == 0) snzw[wid] = bal2; }
        __syncthreads();

        // block-serial NMS on warp 0, rows at LDS latency
        if (wid == 0) {
            unsigned rm;
            int lo = 32 * lane;
            if (lo >= nval) rm = FULL;
            else if (lo + 32 <= nval) rm = 0u;
            else rm = FULL << (nval - lo);
            unsigned removed = rm;

            int nbk = (nval + 31) >> 5;
            for (int bk = 0; bk < nbk; ++bk) {
                unsigned curw = __shfl_sync(FULL, removed, bk);
                unsigned kept = 0;
                if (lane == 0) {
                    const uint4* dg = (const uint4*)(sdiagc + bk * 32);
                    uint4 v0 = dg[0], v1 = dg[1], v2 = dg[2], v3 = dg[3];
                    uint4 v4 = dg[4], v5 = dg[5], v6 = dg[6], v7 = dg[7];
                    unsigned anyd = (v0.x|v0.y|v0.z|v0.w)|(v1.x|v1.y|v1.z|v1.w)
                                  | (v2.x|v2.y|v2.z|v2.w)|(v3.x|v3.y|v3.z|v3.w)
                                  | (v4.x|v4.y|v4.z|v4.w)|(v5.x|v5.y|v5.z|v5.w)
                                  | (v6.x|v6.y|v6.z|v6.w)|(v7.x|v7.y|v7.z|v7.w);
                    if (anyd == 0u) {
                        kept = ~curw;
                    } else {
                        unsigned rem = curw;
                        const uint4 vv[8] = {v0,v1,v2,v3,v4,v5,v6,v7};
#pragma unroll
                        for (int qq = 0; qq < 8; ++qq) {
                            int j0 = qq * 4;
                            if (!((rem >> (j0+0)) & 1u)) { kept |= 1u << (j0+0); rem |= vv[qq].x; }
                            if (!((rem >> (j0+1)) & 1u)) { kept |= 1u << (j0+1); rem |= vv[qq].y; }
                            if (!((rem >> (j0+2)) & 1u)) { kept |= 1u << (j0+2); rem |= vv[qq].z; }
                            if (!((rem >> (j0+3)) & 1u)) { kept |= 1u << (j0+3); rem |= vv[qq].w; }
                        }
                    }
                }
                kept = __shfl_sync(FULL, kept, 0);
                unsigned todo = kept & snzw[bk];
                while (todo) {                           // warp-uniform sparse ORs
                    int j = __ffs(todo) - 1; todo &= todo - 1;
                    removed |= smat[(bk * 32 + j) * 32 + lane];
                }
            }
            srem[lane] = removed;
        }
        __syncthreads();

        // outputs for this class (invalid positions pre-removed)
        for (int p = tid; p < nc; p += NT) {
            bool k = ((srem[p >> 5] >> (p & 31)) & 1u) == 0u;
            unsigned rk = sflatc[p];
            float so = k ? gssc[b][rk] : 0.0f;
            float lo2 = k ? (float)gslab[b][rk] : 0.0f;
            float4 bx = gsbox[b][rk];
            if (!k) bx = make_float4(0.f, 0.f, 0.f, 0.f);
            out[(size_t)b * KTOP + rk] = so;
            out[(size_t)(B * KTOP) + (size_t)b * KTOP + rk] = lo2;
            size_t obase = (size_t)(2 * B * KTOP) + ((size_t)b * KTOP + rk) * 4;
            out[obase + 0] = bx.x; out[obase + 1] = bx.y;
            out[obase + 2] = bx.z; out[obase + 3] = bx.w;
        }
    }
}

extern "C" void kernel_launch(void* const* d_in, const int* in_sizes, int n_in,
                              void* d_out, int out_size) {
    (void)in_sizes; (void)n_in; (void)out_size;
    static bool attr_done = false;
    if (!attr_done) {
        cudaFuncSetAttribute(fcos_persist, cudaFuncAttributeMaxDynamicSharedMemorySize,
                             SMEM_TOTAL);
        attr_done = true;
    }
    fcos_persist<<<NCTA, NT, SMEM_TOTAL>>>(
        (const float*)d_in[0], (const float*)d_in[1], (const float*)d_in[2],
        (const float*)d_in[3], (const float*)d_in[4], (float*)d_out);
}

// round 16
// speedup vs baseline: 1.4420x; 1.4420x over previous
#include <cuda_runtime.h>
#include <cstdint>

#define NA     17064
#define KTOP   1000
#define NBINS  16384
#define CCAP   4096
#define NT     1024
#define B      16
#define NCTA   128
#define FULL   0xffffffffu

typedef unsigned long long u64;

// ---------------- static device scratch ----------------
__device__ unsigned ghist[B][NBINS];      // zero-init; re-zeroed each pass
__device__ unsigned gcnt[B];
__device__ u64      gkey[B][CCAP];
__device__ unsigned grank[B][CCAP];       // zeroed in P1 each pass
__device__ unsigned gbarc[B][8];          // per-batch epoch barrier counters

// Exact sigmoid: float exp via double exp (correctly rounded to float =>
// matches faithful libm expf), then float add + div as XLA expands logistic.
__device__ __forceinline__ float sigx(float x) {
    float t = (float)exp(-(double)x);
    return __fdiv_rn(1.0f, __fadd_rn(1.0f, t));
}
// Fast approximate sigmoid — superset selection only.
__device__ __forceinline__ float siga(float x) {
    return __fdividef(1.0f, 1.0f + __expf(-x));
}
// per-batch barrier (8 CTAs), release/acquire, graph-replay safe
__device__ __forceinline__ void bbarrier(int b, int k) {
    __syncthreads();
    if (threadIdx.x == 0) {
        unsigned* addr = &gbarc[b][k];
        unsigned old;
        asm volatile("atom.add.release.gpu.global.u32 %0, [%1], 1;"
                     : "=r"(old) : "l"(addr) : "memory");
        unsigned target = ((old >> 3) + 1u) << 3;
        unsigned v;
        do {
            asm volatile("ld.acquire.gpu.global.u32 %0, [%1];"
                         : "=r"(v) : "l"(addr) : "memory");
        } while (v < target);
    }
    __syncthreads();
}
// guarded warp suffix-sum (inclusive from high lanes)
__device__ __forceinline__ unsigned suffix_sum(unsigned v, int lane) {
#pragma unroll
    for (int o = 1; o < 32; o <<= 1) {
        unsigned t = __shfl_down_sync(FULL, v, o);
        if (lane + o < 32) v += t;
    }
    return v;
}

// ---- dynamic smem arena (bytes) ----
#define OFF_MAT    0          // u32[1000][32] = 128000 | P3: keys u64[4096]=32KB
#define OFF_BX     128000     // 5 * f32[1000] = 20000  (offset boxes + area)
#define OFF_BOX4   148000     // float4[1000]  = 16000  (clipped boxes)
#define OFF_KEY    164000     // u64[1000]     = 8000
#define OFF_FLAT   172000     // u32[1000]     = 4000
#define OFF_DIAG   176000     // u32[1024]     = 4096
#define OFF_RNZ    180096     // u32[1024]     = 4096
#define SMEM_TOTAL 184192
extern __shared__ unsigned char smem_raw[];

__global__ void __launch_bounds__(NT, 1)
fcos_persist(const float* __restrict__ cls, const float* __restrict__ ctr,
             const float* __restrict__ reg, const float* __restrict__ coords,
             const float* __restrict__ pstr, float* __restrict__ out)
{
    const int cta  = blockIdx.x;
    const int b    = cta >> 3;
    const int r    = cta & 7;
    const int tid  = threadIdx.x;
    const int lane = tid & 31;
    const int wid  = tid >> 5;

    __shared__ unsigned chunk[1024];
    __shared__ unsigned supr[32];
    __shared__ float redmax[32], redmin[32];
    __shared__ float s_mx, s_mn;
    __shared__ unsigned s_thr;
    __shared__ unsigned swcnt2[32], swv2[32], soff2[32];
    __shared__ unsigned s_nc, s_nval;
    __shared__ unsigned snzw[32], srem[32];

    const float4* clsB = (const float4*)cls + (size_t)b * NA;
    const float*  ctrB = ctr + (size_t)b * NA;

    // ============ P1: zero scratch + approx-score histogram ================
    if (r == 0 && tid == 0) gcnt[b] = 0;
    if (tid < 512) grank[b][r * 512 + tid] = 0u;
    for (int i = r * NT + tid; i < NA; i += 8 * NT) {
        float4 c = clsB[i];
        float m = fmaxf(fmaxf(c.x, c.y), fmaxf(c.z, c.w));   // sigmoid monotone
        float score = __fsqrt_rn(siga(m) * siga(ctrB[i]));
        atomicAdd(&ghist[b][__float_as_uint(score) >> 16], 1u);
    }
    bbarrier(b, 0);

    // ============ P2: threshold (warp-parallel suffix scans) ================
    { unsigned s = 0; int base = tid * 16;
#pragma unroll
      for (int q = 0; q < 16; ++q) s += ghist[b][base + q];
      chunk[tid] = s; }
    __syncthreads();
    { unsigned s = chunk[wid * 32 + lane];
#pragma unroll
      for (int o = 16; o; o >>= 1) s += __shfl_xor_sync(FULL, s, o);
      if (lane == 0) supr[wid] = s; }
    __syncthreads();
    if (wid == 0) {
        unsigned suf = suffix_sum(supr[lane], lane);
        unsigned m1  = __ballot_sync(FULL, suf >= KTOP);
        int sblk     = 31 - __clz(m1);
        unsigned above = (sblk < 31) ? __shfl_sync(FULL, suf, sblk + 1) : 0u;
        unsigned cs  = suffix_sum(chunk[sblk * 32 + lane], lane);
        unsigned m2  = __ballot_sync(FULL, cs + above >= KTOP);
        int cc       = 31 - __clz(m2);
        unsigned above2 = above + ((cc < 31) ? __shfl_sync(FULL, cs, cc + 1) : 0u);
        int binbase  = (sblk * 32 + cc) * 16;
        unsigned bs  = suffix_sum((lane < 16) ? ghist[b][binbase + lane] : 0u, lane);
        unsigned m3  = __ballot_sync(FULL, bs + above2 >= KTOP);
        int bb       = 31 - __clz(m3);
        if (lane == 0) {
            int T = binbase + bb;
            s_thr = (T > 0) ? (unsigned)(T - 1) : 0u;   // one-bin superset margin
        }
    }
    __syncthreads();
    const unsigned T = s_thr;

    // ============ P2b: fused compact + exact rescore ========================
    for (int i = r * NT + tid; i < NA; i += 8 * NT) {
        float4 c = clsB[i];
        float xs0 = c.x, xs1 = c.y, xs2 = c.z, xs3 = c.w;
        float m = fmaxf(fmaxf(xs0, xs1), fmaxf(xs2, xs3));
        float ctrv = ctrB[i];
        float sa = __fsqrt_rn(siga(m) * siga(ctrv));
        if ((__float_as_uint(sa) >> 16) >= T) {
            unsigned p = atomicAdd(&gcnt[b], 1u);
            if (p < CCAP) {
                int im = 0; float mm = xs0;
                if (xs1 > mm) { mm = xs1; im = 1; }
                if (xs2 > mm) { mm = xs2; im = 2; }
                if (xs3 > mm) { mm = xs3; im = 3; }
                float sm = sigx(mm);                    // == max of 4 sigmoids
                int lab = im;
                if (im > 0) {                           // first-argmax tie guard
                    float lim = mm - 1e-4f;
                    if (xs0 > lim || (im > 1 && xs1 > lim) || (im > 2 && xs2 > lim)) {
                        if (xs0 > lim && sigx(xs0) == sm) lab = 0;
                        else if (im > 1 && xs1 > lim && sigx(xs1) == sm) lab = 1;
                        else if (im > 2 && xs2 > lim && sigx(xs2) == sm) lab = 2;
                    }
                }
                float sctr  = sigx(ctrv);
                float score = __fsqrt_rn(__fmul_rn(sm, sctr));
                gkey[b][p] = ((u64)__float_as_uint(score) << 32)
                           | ((u64)(0x7FFFu - (unsigned)i) << 4) | (u64)(lab + 1);
            }
        }
    }
    bbarrier(b, 1);

    int C = (int)gcnt[b]; if (C > CCAP) C = CCAP;

    // ============ P3: brute-force rank (8 CTAs, O(C^2)/8 each) ==============
    {
        u64* skeys = (u64*)smem_raw;
        for (int i = tid; i < C; i += NT) skeys[i] = gkey[b][i];
        __syncthreads();
        int j0 = (r * C) >> 3, j1 = ((r + 1) * C) >> 3;
        for (int i = tid; i < C; i += NT) {
            u64 ki = skeys[i];
            unsigned cnt = 0;
#pragma unroll 8
            for (int j = j0; j < j1; ++j) cnt += (skeys[j] > ki) ? 1u : 0u;
            if (cnt) atomicAdd(&grank[b][i], cnt);
        }
    }
    bbarrier(b, 2);

    // ============ P4: non-class CTAs zero hist then exit ====================
    if (r >= 4) {
        int z0 = (r - 4) * 4096;
        for (int i = z0 + tid; i < z0 + 4096; i += NT) ghist[b][i] = 0;
        return;
    }

    // ============ P5: class CTA (c = r): gather + matrix + NMS + outputs ====
    {
        unsigned* smat  = (unsigned*)(smem_raw + OFF_MAT);   // [1000][32]
        float* sx1c = (float*)(smem_raw + OFF_BX);
        float* sy1c = sx1c + KTOP; float* sx2c = sy1c + KTOP;
        float* sy2c = sx2c + KTOP; float* sarc = sy2c + KTOP;
        float4* sbox4 = (float4*)(smem_raw + OFF_BOX4);
        u64* skey = (u64*)(smem_raw + OFF_KEY);
        unsigned* sflatc = (unsigned*)(smem_raw + OFF_FLAT);
        unsigned* sdiagc = (unsigned*)(smem_raw + OFF_DIAG);
        unsigned* srownz = (unsigned*)(smem_raw + OFF_RNZ);

        const int c = r;

        // scatter rank<KTOP keys into smem (ranks unique -> race-free)
        if (tid < KTOP) skey[tid] = 0ULL;
        __syncthreads();
        for (int i = tid; i < C; i += NT) {
            unsigned rk = grank[b][i];
            if (rk < KTOP) skey[rk] = gkey[b][i];
        }
        __syncthreads();

        // build all clipped boxes (1 per thread), validity, mx/mn, membership
        int q = tid;
        u64 key = (q < KTOP) ? skey[q] : 0ULL;
        float score = __uint_as_float((unsigned)(key >> 32));
        int label   = (int)(key & 0xFull);
        bool validf = (q < KTOP) && (score >= 0.05f);
        bool member = (q < KTOP) && (label == c + 1);
        float x1 = 0, y1 = 0, x2 = 0, y2 = 0;
        if (q < KTOP && label > 0) {
            int idx = 0x7FFF - (int)((key >> 4) & 0x7FFFull);
            float4 r4 = ((const float4*)reg)[(size_t)b * NA + idx];
            float2 xy = ((const float2*)coords)[idx];
            float  st = pstr[idx];
            x1 = __fsub_rn(xy.x, __fmul_rn(r4.x, st));
            y1 = __fsub_rn(xy.y, __fmul_rn(r4.y, st));
            x2 = __fadd_rn(xy.x, __fmul_rn(r4.z, st));
            y2 = __fadd_rn(xy.y, __fmul_rn(r4.w, st));
            x1 = fminf(fmaxf(x1, 0.0f), 1023.0f);
            y1 = fminf(fmaxf(y1, 0.0f), 799.0f);
            x2 = fminf(fmaxf(x2, 0.0f), 1023.0f);
            y2 = fminf(fmaxf(y2, 0.0f), 799.0f);
        }
        if (q < KTOP) sbox4[q] = make_float4(x1, y1, x2, y2);

        unsigned bal  = __ballot_sync(FULL, member);
        unsigned balv = __ballot_sync(FULL, member && validf);
        if (lane == 0) { swcnt2[wid] = __popc(bal); swv2[wid] = __popc(balv); }

        float vmax = -1000000000.0f, vmin = 1000000000.0f;
        if (validf) {
            vmax = fmaxf(fmaxf(x1, y1), fmaxf(x2, y2));
            vmin = fminf(fminf(x1, y1), fminf(x2, y2));
        }
#pragma unroll
        for (int o = 16; o; o >>= 1) {
            vmax = fmaxf(vmax, __shfl_xor_sync(FULL, vmax, o));
            vmin = fminf(vmin, __shfl_xor_sync(FULL, vmin, o));
        }
        if (lane == 0) { redmax[wid] = vmax; redmin[wid] = vmin; }
        __syncthreads();

        if (wid == 0) {
            // class prefix over warps
            unsigned v = swcnt2[lane];
            unsigned inc = v;
#pragma unroll
            for (int o = 1; o < 32; o <<= 1) {
                unsigned t2 = __shfl_up_sync(FULL, inc, o);
                if (lane >= o) inc += t2;
            }
            soff2[lane] = inc - v;
            unsigned tv = swv2[lane];
#pragma unroll
            for (int o = 16; o; o >>= 1) tv += __shfl_xor_sync(FULL, tv, o);
            if (lane == 31) s_nc = inc;
            if (lane == 0)  s_nval = tv;
        } else if (wid == 1) {
            float mx = redmax[lane], mn = redmin[lane];
#pragma unroll
            for (int o = 16; o; o >>= 1) {
                mx = fmaxf(mx, __shfl_xor_sync(FULL, mx, o));
                mn = fminf(mn, __shfl_xor_sync(FULL, mn, o));
            }
            if (lane == 0) { s_mx = mx; s_mn = mn; }
        }
        __syncthreads();
        const int nc   = (int)s_nc;
        const int nval = (int)s_nval;
        float off = __fmul_rn((float)(c + 1), __fadd_rn(__fsub_rn(s_mx, s_mn), 1.0f));

        if (member) {
            unsigned pos = soff2[wid] + __popc(bal & ((1u << lane) - 1u));
            float a  = __fadd_rn(x1, off), bb2 = __fadd_rn(y1, off);
            float cc3 = __fadd_rn(x2, off), dd = __fadd_rn(y2, off);
            sx1c[pos] = a;  sy1c[pos] = bb2;
            sx2c[pos] = cc3; sy2c[pos] = dd;
            sarc[pos] = __fmul_rn(__fsub_rn(cc3, a), __fsub_rn(dd, bb2));
            sflatc[pos] = (unsigned)q;
        }
        __syncthreads();

        // matrix in smem: warp per row
        int nw = (nc + 31) >> 5;
        for (int pos = wid; pos < nc; pos += 32) {
            float ax1 = sx1c[pos], ay1 = sy1c[pos], ax2 = sx2c[pos],
                  ay2 = sy2c[pos], aa = sarc[pos];
            unsigned myword = 0;
            int jc0 = (pos + 1) >> 5;
            for (int jc = jc0; jc < nw; ++jc) {
                int j = jc * 32 + lane;
                bool sup = false;
                if (j > pos && j < nc) {
                    float ix1 = fmaxf(ax1, sx1c[j]);
                    float iy1 = fmaxf(ay1, sy1c[j]);
                    float ix2 = fminf(ax2, sx2c[j]);
                    float iy2 = fminf(ay2, sy2c[j]);
                    float iw  = fmaxf(__fsub_rn(ix2, ix1), 0.0f);
                    float ih  = fmaxf(__fsub_rn(iy2, iy1), 0.0f);
                    float inter = __fmul_rn(iw, ih);
                    float uni = fmaxf(__fsub_rn(__fadd_rn(aa, sarc[j]), inter), 1e-9f);
                    sup = __fdiv_rn(inter, uni) > 0.5f;
                }
                unsigned wbits = __ballot_sync(FULL, sup);
                if (lane == jc) myword = wbits;
            }
            smat[pos * 32 + lane] = myword;
            if (lane == (pos >> 5)) sdiagc[pos] = myword;
            unsigned any = __ballot_sync(FULL, myword != 0u);
            if (lane == 0) srownz[pos] = any;
        }
        __syncthreads();

        // per-block nz words (single full-block trip, nc <= 1000 < NT)
        { unsigned v = (tid < nc) ? srownz[tid] : 0u;
          unsigned bal2 = __ballot_sync(FULL, v != 0u);
          if (lane == 0) snzw[wid] = bal2; }
        __syncthreads();

        // block-serial NMS on warp 0, rows at LDS latency
        if (wid == 0) {
            unsigned rm;
            int lo = 32 * lane;
            if (lo >= nval) rm = FULL;
            else if (lo + 32 <= nval) rm = 0u;
            else rm = FULL << (nval - lo);
            unsigned removed = rm;

            int nbk = (nval + 31) >> 5;
            for (int bk = 0; bk < nbk; ++bk) {
                unsigned curw = __shfl_sync(FULL, removed, bk);
                unsigned kept = 0;
                if (lane == 0) {
                    const uint4* dg = (const uint4*)(sdiagc + bk * 32);
                    uint4 v0 = dg[0], v1 = dg[1], v2 = dg[2], v3 = dg[3];
                    uint4 v4 = dg[4], v5 = dg[5], v6 = dg[6], v7 = dg[7];
                    unsigned anyd = (v0.x|v0.y|v0.z|v0.w)|(v1.x|v1.y|v1.z|v1.w)
                                  | (v2.x|v2.y|v2.z|v2.w)|(v3.x|v3.y|v3.z|v3.w)
                                  | (v4.x|v4.y|v4.z|v4.w)|(v5.x|v5.y|v5.z|v5.w)
                                  | (v6.x|v6.y|v6.z|v6.w)|(v7.x|v7.y|v7.z|v7.w);
                    if (anyd == 0u) {
                        kept = ~curw;
                    } else {
                        unsigned rem = curw;
                        const uint4 vv[8] = {v0,v1,v2,v3,v4,v5,v6,v7};
#pragma unroll
                        for (int qq = 0; qq < 8; ++qq) {
                            int j0 = qq * 4;
                            if (!((rem >> (j0+0)) & 1u)) { kept |= 1u << (j0+0); rem |= vv[qq].x; }
                            if (!((rem >> (j0+1)) & 1u)) { kept |= 1u << (j0+1); rem |= vv[qq].y; }
                            if (!((rem >> (j0+2)) & 1u)) { kept |= 1u << (j0+2); rem |= vv[qq].z; }
                            if (!((rem >> (j0+3)) & 1u)) { kept |= 1u << (j0+3); rem |= vv[qq].w; }
                        }
                    }
                }
                kept = __shfl_sync(FULL, kept, 0);
                unsigned todo = kept & snzw[bk];
                while (todo) {                           // warp-uniform sparse ORs
                    int j = __ffs(todo) - 1; todo &= todo - 1;
                    removed |= smat[(bk * 32 + j) * 32 + lane];
                }
            }
            srem[lane] = removed;
        }
        __syncthreads();

        // outputs for this class (invalid positions pre-removed)
        for (int p = tid; p < nc; p += NT) {
            bool k = ((srem[p >> 5] >> (p & 31)) & 1u) == 0u;
            unsigned rk = sflatc[p];
            u64 kk = skey[rk];
            float so = k ? __uint_as_float((unsigned)(kk >> 32)) : 0.0f;
            float lo2 = k ? (float)(c + 1) : 0.0f;
            float4 bx = sbox4[rk];
            if (!k) bx = make_float4(0.f, 0.f, 0.f, 0.f);
            out[(size_t)b * KTOP + rk] = so;
            out[(size_t)(B * KTOP) + (size_t)b * KTOP + rk] = lo2;
            size_t obase = (size_t)(2 * B * KTOP) + ((size_t)b * KTOP + rk) * 4;
            out[obase + 0] = bx.x; out[obase + 1] = bx.y;
            out[obase + 2] = bx.z; out[obase + 3] = bx.w;
        }
        // CTA of class 0 zeroes unfilled-rank slots (label == 0)
        if (c == 0 && tid < KTOP) {
            if ((skey[tid] & 0xFull) == 0ULL) {
                out[(size_t)b * KTOP + tid] = 0.0f;
                out[(size_t)(B * KTOP) + (size_t)b * KTOP + tid] = 0.0f;
                size_t obase = (size_t)(2 * B * KTOP) + ((size_t)b * KTOP + tid) * 4;
                out[obase + 0] = 0.0f; out[obase + 1] = 0.0f;
                out[obase + 2] = 0.0f; out[obase + 3] = 0.0f;
            }
        }
    }
}

extern "C" void kernel_launch(void* const* d_in, const int* in_sizes, int n_in,
                              void* d_out, int out_size) {
    (void)in_sizes; (void)n_in; (void)out_size;
    static bool attr_done = false;
    if (!attr_done) {
        cudaFuncSetAttribute(fcos_persist, cudaFuncAttributeMaxDynamicSharedMemorySize,
                             SMEM_TOTAL);
        attr_done = true;
    }
    fcos_persist<<<NCTA, NT, SMEM_TOTAL>>>(
        (const float*)d_in[0], (const float*)d_in[1], (const float*)d_in[2],
        (const float*)d_in[3], (const float*)d_in[4], (float*)d_out);
}